// round 17
// baseline (speedup 1.0000x reference)
#include <cuda_runtime.h>
#include <cuda_bf16.h>
#include <math.h>

#define B_    2
#define S_    2048
#define D_    768
#define H_    12
#define DEP_  64
#define BH_   (B_*H_)            // 24
#define MROWS (B_*S_)            // 4096
#define OUT_ELEMS (B_*S_*D_)     // 3145728
#define ATTN_ELEMS (BH_*S_*S_)   // 100663296
#define NCHUNK 64                // 2048/32 : one chunk = 32 columns
#define TOTROWS (BH_*S_)         // 49152

#define DYN_SMEM_BYTES 61440     // 15360 words, all three mma kernels

// ---- scratch (alloc-free, __device__ globals) ----
__device__ float g_Qp[BH_*S_*DEP_];
__device__ float g_Kp[BH_*S_*DEP_];
__device__ float g_ctx[MROWS*D_];
__device__ float g_rowmax[TOTROWS];
__device__ float g_rowinv[TOTROWS];
__device__ float g_cmax[NCHUNK*TOTROWS];   // chunk-major: [chunk][row]
__device__ float g_csum[NCHUNK*TOTROWS];
__device__ unsigned g_Vth[BH_*DEP_*(S_/2)];
__device__ unsigned g_Vtl[BH_*DEP_*(S_/2)];
__device__ float g_attn_scratch[ATTN_ELEMS];

__device__ __forceinline__ float neg_inf() { return __int_as_float(0xff800000); }

__device__ __forceinline__ void split2(float x, float y, unsigned& h, unsigned& l) {
    __nv_bfloat162 hv = __floats2bfloat162_rn(x, y);
    float2 hf = __bfloat1622float2(hv);
    __nv_bfloat162 lv = __floats2bfloat162_rn(x - hf.x, y - hf.y);
    h = *(unsigned*)&hv;
    l = *(unsigned*)&lv;
}

__device__ __forceinline__ void mma16(float* c,
                                      unsigned a0, unsigned a1, unsigned a2, unsigned a3,
                                      unsigned b0, unsigned b1) {
    asm volatile(
        "mma.sync.aligned.m16n8k16.row.col.f32.bf16.bf16.f32 "
        "{%0,%1,%2,%3}, {%4,%5,%6,%7}, {%8,%9}, {%0,%1,%2,%3};\n"
        : "+f"(c[0]), "+f"(c[1]), "+f"(c[2]), "+f"(c[3])
        : "r"(a0), "r"(a1), "r"(a2), "r"(a3), "r"(b0), "r"(b1));
}

__device__ __forceinline__ void ldsm_x4(unsigned* r, const void* p) {
    unsigned addr = (unsigned)__cvta_generic_to_shared(p);
    asm volatile("ldmatrix.sync.aligned.m8n8.x4.shared.b16 {%0,%1,%2,%3}, [%4];"
        : "=r"(r[0]), "=r"(r[1]), "=r"(r[2]), "=r"(r[3]) : "r"(addr));
}

// 24 mmas of one k16-step, product-major
#define MMA_STEP_PRODMAJOR(acc, ah, al, bhf, blf)                              \
    do {                                                                       \
        _Pragma("unroll")                                                      \
        for (int nt = 0; nt < 4; nt++) {                                       \
            const unsigned b0 = bhf[nt>>1][(nt&1)*2], b1 = bhf[nt>>1][(nt&1)*2+1]; \
            _Pragma("unroll")                                                  \
            for (int mt = 0; mt < 2; mt++)                                     \
                mma16(acc[mt][nt], ah[mt][0],ah[mt][1],ah[mt][2],ah[mt][3], b0, b1); \
        }                                                                      \
        _Pragma("unroll")                                                      \
        for (int nt = 0; nt < 4; nt++) {                                       \
            const unsigned b0 = blf[nt>>1][(nt&1)*2], b1 = blf[nt>>1][(nt&1)*2+1]; \
            _Pragma("unroll")                                                  \
            for (int mt = 0; mt < 2; mt++)                                     \
                mma16(acc[mt][nt], ah[mt][0],ah[mt][1],ah[mt][2],ah[mt][3], b0, b1); \
        }                                                                      \
        _Pragma("unroll")                                                      \
        for (int nt = 0; nt < 4; nt++) {                                       \
            const unsigned b0 = bhf[nt>>1][(nt&1)*2], b1 = bhf[nt>>1][(nt&1)*2+1]; \
            _Pragma("unroll")                                                  \
            for (int mt = 0; mt < 2; mt++)                                     \
                mma16(acc[mt][nt], al[mt][0],al[mt][1],al[mt][2],al[mt][3], b0, b1); \
        }                                                                      \
    } while (0)

// ======================================================================
// Fused Q/K/V projection GEMM (R16): grid.z selects projection.
// ======================================================================
__global__ __launch_bounds__(256, 2)
void gemm_xwT_bf16(const float* __restrict__ X0, const float* __restrict__ X1,
                   const float* __restrict__ X2,
                   const float* __restrict__ W0, const float* __restrict__ W1,
                   const float* __restrict__ W2,
                   const float* __restrict__ bias0, const float* __restrict__ bias1,
                   const float* __restrict__ bias2,
                   float* __restrict__ C0, float* __restrict__ C1,
                   unsigned* __restrict__ Vth, unsigned* __restrict__ Vtl,
                   int K, int N, int fused)
{
    extern __shared__ unsigned dsm[];

    const int t = threadIdx.x, wid = t >> 5, lane = t & 31;
    const int gid = lane >> 2, tig = lane & 3;
    const int n0 = blockIdx.x * 64, m0 = blockIdx.y * 128;
    const int z  = blockIdx.z;
    const int wm = (wid & 3) * 32, wn = (wid >> 2) * 32;

    const float* X    = (z == 0) ? X0 : (z == 1) ? X1 : X2;
    const float* W    = (z == 0) ? W0 : (z == 1) ? W1 : W2;
    const float* bias = (z == 0) ? bias0 : (z == 1) ? bias1 : bias2;
    const int   mode  = fused ? ((z == 2) ? 3 : 1) : 0;
    const float alpha = (fused && z == 0) ? 0.125f : 1.0f;
    float* C          = (z == 0) ? C0 : C1;

    const int a_r = lane & 15, a_c = ((lane >> 4) & 1) * 4;
    const int b_r = (lane & 7) + ((lane >> 4) & 1) * 8;
    const int b_c = ((lane >> 3) & 1) * 4;

    const int lr = t >> 1, lg = t & 1;
    const int br = t >> 2, bg = t & 3;

    const float* Xp = X + (size_t)(m0 + lr) * K + lg * 16;
    const float* Wp = W + (size_t)(n0 + br) * K + bg * 8;

    float acc[2][4][4];
#pragma unroll
    for (int i = 0; i < 2; i++)
#pragma unroll
        for (int j = 0; j < 4; j++)
#pragma unroll
            for (int q = 0; q < 4; q++) acc[i][j][q] = 0.0f;

    const int NS = K / 32;

    float4 xa[4], wb[2];
#pragma unroll
    for (int j = 0; j < 4; j++) xa[j] = *(const float4*)(Xp + j * 4);
#pragma unroll
    for (int j = 0; j < 2; j++) wb[j] = *(const float4*)(Wp + j * 4);

    {
        unsigned* AH = dsm;            unsigned* AL = dsm + 2560;
        unsigned* BH = dsm + 5120;     unsigned* BL = dsm + 6400;
#pragma unroll
        for (int j = 0; j < 4; j++) {
            unsigned h, l;
            split2(xa[j].x, xa[j].y, h, l);
            AH[lr*20 + lg*8 + 2*j]   = h;  AL[lr*20 + lg*8 + 2*j]   = l;
            split2(xa[j].z, xa[j].w, h, l);
            AH[lr*20 + lg*8 + 2*j+1] = h;  AL[lr*20 + lg*8 + 2*j+1] = l;
        }
#pragma unroll
        for (int j = 0; j < 2; j++) {
            unsigned h, l;
            split2(wb[j].x, wb[j].y, h, l);
            BH[br*20 + bg*4 + 2*j]   = h;  BL[br*20 + bg*4 + 2*j]   = l;
            split2(wb[j].z, wb[j].w, h, l);
            BH[br*20 + bg*4 + 2*j+1] = h;  BL[br*20 + bg*4 + 2*j+1] = l;
        }
    }
    __syncthreads();

#pragma unroll 1
    for (int s = 0; s < NS; s++) {
        const int st = s & 1;
        const unsigned base = st * 7680;

        if (s + 1 < NS) {
            const int k0 = (s + 1) * 32;
#pragma unroll
            for (int j = 0; j < 4; j++) xa[j] = *(const float4*)(Xp + k0 + j * 4);
#pragma unroll
            for (int j = 0; j < 2; j++) wb[j] = *(const float4*)(Wp + k0 + j * 4);
        }

#pragma unroll
        for (int step = 0; step < 2; step++) {
            const int kc = step * 8;
            unsigned ah[2][4], al[2][4], bhf[2][4], blf[2][4];
#pragma unroll
            for (int mt = 0; mt < 2; mt++) {
                ldsm_x4(ah[mt], dsm + base + (wm + mt*16 + a_r)*20 + kc + a_c);
                ldsm_x4(al[mt], dsm + base + 2560 + (wm + mt*16 + a_r)*20 + kc + a_c);
            }
#pragma unroll
            for (int np = 0; np < 2; np++) {
                ldsm_x4(bhf[np], dsm + base + 5120 + (wn + np*16 + b_r)*20 + kc + b_c);
                ldsm_x4(blf[np], dsm + base + 6400 + (wn + np*16 + b_r)*20 + kc + b_c);
            }
            MMA_STEP_PRODMAJOR(acc, ah, al, bhf, blf);
        }

        if (s + 1 < NS) {
            const unsigned nb = (st ^ 1) * 7680;
            unsigned* AH = dsm + nb;          unsigned* AL = dsm + nb + 2560;
            unsigned* BH = dsm + nb + 5120;   unsigned* BL = dsm + nb + 6400;
#pragma unroll
            for (int j = 0; j < 4; j++) {
                unsigned h, l;
                split2(xa[j].x, xa[j].y, h, l);
                AH[lr*20 + lg*8 + 2*j]   = h;  AL[lr*20 + lg*8 + 2*j]   = l;
                split2(xa[j].z, xa[j].w, h, l);
                AH[lr*20 + lg*8 + 2*j+1] = h;  AL[lr*20 + lg*8 + 2*j+1] = l;
            }
#pragma unroll
            for (int j = 0; j < 2; j++) {
                unsigned h, l;
                split2(wb[j].x, wb[j].y, h, l);
                BH[br*20 + bg*4 + 2*j]   = h;  BL[br*20 + bg*4 + 2*j]   = l;
                split2(wb[j].z, wb[j].w, h, l);
                BH[br*20 + bg*4 + 2*j+1] = h;  BL[br*20 + bg*4 + 2*j+1] = l;
            }
        }
        __syncthreads();
    }

    if (mode == 3) {
        float* tf = (float*)dsm;   // [128][65] fp32 tile
#pragma unroll
        for (int mt = 0; mt < 2; mt++) {
#pragma unroll
            for (int nt = 0; nt < 4; nt++) {
                const int rl0 = wm + mt*16 + gid;
                const int rl1 = rl0 + 8;
                const int cl  = wn + nt*8 + tig*2;
                const float b0v = bias[n0 + cl], b1v = bias[n0 + cl + 1];
                tf[rl0*65 + cl]     = acc[mt][nt][0] + b0v;
                tf[rl0*65 + cl + 1] = acc[mt][nt][1] + b1v;
                tf[rl1*65 + cl]     = acc[mt][nt][2] + b0v;
                tf[rl1*65 + cl + 1] = acc[mt][nt][3] + b1v;
            }
        }
        __syncthreads();
        const int bb = m0 / S_, hh = n0 / DEP_;
        const int bh = bb * H_ + hh;
        const int p0 = (m0 % S_) / 2;
#pragma unroll
        for (int i = 0; i < 16; i++) {
            const int idx = t + i * 256;
            const int p = idx & 63;
            const int d = idx >> 6;
            unsigned h2, l2;
            split2(tf[(2*p)*65 + d], tf[(2*p + 1)*65 + d], h2, l2);
            const size_t o = ((size_t)bh * DEP_ + d) * (S_/2) + p0 + p;
            Vth[o] = h2;
            Vtl[o] = l2;
        }
        return;
    }

#pragma unroll
    for (int mt = 0; mt < 2; mt++) {
#pragma unroll
        for (int nt = 0; nt < 4; nt++) {
            const int r0 = m0 + wm + mt*16 + gid;
            const int r1 = r0 + 8;
            const int c  = n0 + wn + nt*8 + tig*2;
            const float b0v = bias[c], b1v = bias[c+1];
            float2 v0, v1;
            v0.x = alpha * (acc[mt][nt][0] + b0v);
            v0.y = alpha * (acc[mt][nt][1] + b1v);
            v1.x = alpha * (acc[mt][nt][2] + b0v);
            v1.y = alpha * (acc[mt][nt][3] + b1v);
            if (mode == 1) {
                const int h = n0 / DEP_;
                const int dd = c - n0;
                const int b0_ = r0 / S_, s0 = r0 % S_;
                const int b1_ = r1 / S_, s1 = r1 % S_;
                *(float2*)(C + (((size_t)(b0_*H_ + h))*S_ + s0)*DEP_ + dd) = v0;
                *(float2*)(C + (((size_t)(b1_*H_ + h))*S_ + s1)*DEP_ + dd) = v1;
            } else {
                *(float2*)(C + (size_t)r0 * N + c) = v0;
                *(float2*)(C + (size_t)r1 * N + c) = v1;
            }
        }
    }
}

// ======================================================================
// logits: 128m x 256n strip. Writes p' = exp(x - chunk_max) to attn
// (0 for masked) and per-(row, 32-col-chunk) max/sum to cmax/csum
// (chunk-major). grid (8, 16, 24)
// ======================================================================
__global__ __launch_bounds__(256, 2)
void logits_bf16(const float* __restrict__ Qp,
                 const float* __restrict__ Kp,
                 const int*   __restrict__ mask,
                 float* __restrict__ attn,
                 float* __restrict__ cmax,
                 float* __restrict__ csum)
{
    extern __shared__ unsigned dsm[];
    __shared__ int smask[256];

    const int t = threadIdx.x, wid = t >> 5, lane = t & 31;
    const int gid = lane >> 2, tig = lane & 3;
    const int nbase = blockIdx.x * 256, m0 = blockIdx.y * 128;
    const int bh = blockIdx.z, b = bh / H_;
    const int wm = (wid & 3) * 32, wn = (wid >> 2) * 32;
    const int hf = wid >> 2;

    const int a_r = lane & 15, a_c = ((lane >> 4) & 1) * 4;
    const int b_r = (lane & 7) + ((lane >> 4) & 1) * 8;
    const int b_c = ((lane >> 3) & 1) * 4;

    smask[t] = mask[b * S_ + nbase + t];

    const int br = t >> 2, bg = t & 3;

    // ---- A: load full K=64 into smem (slab = t&1, row = t>>1)
    {
        const int slab = t & 1, row = t >> 1;
        const float* Qb = Qp + ((size_t)bh * S_ + m0 + row) * DEP_ + slab * 32;
        unsigned* AH = dsm + slab * 2560;
        unsigned* AL = dsm + 5120 + slab * 2560;
#pragma unroll
        for (int g = 0; g < 4; g++) {
            float4 f0 = *(const float4*)(Qb + g * 8);
            float4 f1 = *(const float4*)(Qb + g * 8 + 4);
            unsigned h, l;
            split2(f0.x, f0.y, h, l);
            AH[row*20 + g*4 + 0] = h;  AL[row*20 + g*4 + 0] = l;
            split2(f0.z, f0.w, h, l);
            AH[row*20 + g*4 + 1] = h;  AL[row*20 + g*4 + 1] = l;
            split2(f1.x, f1.y, h, l);
            AH[row*20 + g*4 + 2] = h;  AL[row*20 + g*4 + 2] = l;
            split2(f1.z, f1.w, h, l);
            AH[row*20 + g*4 + 3] = h;  AL[row*20 + g*4 + 3] = l;
        }
    }

    // ---- B it=0 load + store into stage 0
    float4 wb[2];
    {
        const float* Kb = Kp + ((size_t)bh * S_ + nbase + br) * DEP_ + bg * 8;
#pragma unroll
        for (int j = 0; j < 2; j++) wb[j] = *(const float4*)(Kb + j * 4);
        unsigned* BH = dsm + 10240;
        unsigned* BL = dsm + 10240 + 1280;
#pragma unroll
        for (int j = 0; j < 2; j++) {
            unsigned h, l;
            split2(wb[j].x, wb[j].y, h, l);
            BH[br*20 + bg*4 + 2*j]   = h;  BL[br*20 + bg*4 + 2*j]   = l;
            split2(wb[j].z, wb[j].w, h, l);
            BH[br*20 + bg*4 + 2*j+1] = h;  BL[br*20 + bg*4 + 2*j+1] = l;
        }
    }
    __syncthreads();

    float acc[2][4][4];
    float* Cb = attn + (size_t)bh * S_ * S_;

#pragma unroll
    for (int it = 0; it < 8; it++) {
        const int ni = it >> 1, ks = it & 1, st = it & 1;
        if (ks == 0) {
#pragma unroll
            for (int i = 0; i < 2; i++)
#pragma unroll
                for (int j = 0; j < 4; j++)
#pragma unroll
                    for (int q = 0; q < 4; q++) acc[i][j][q] = 0.0f;
        }

        if (it + 1 < 8) {
            const int niN = (it+1) >> 1, ksN = (it+1) & 1;
            const float* Kb = Kp + ((size_t)bh * S_ + nbase + niN*64 + br) * DEP_
                              + ksN*32 + bg*8;
#pragma unroll
            for (int j = 0; j < 2; j++) wb[j] = *(const float4*)(Kb + j * 4);
        }

#pragma unroll
        for (int step = 0; step < 2; step++) {
            const int kc = step * 8;
            unsigned ah[2][4], al[2][4], bhf[2][4], blf[2][4];
#pragma unroll
            for (int mt = 0; mt < 2; mt++) {
                ldsm_x4(ah[mt], dsm + ks*2560        + (wm + mt*16 + a_r)*20 + kc + a_c);
                ldsm_x4(al[mt], dsm + 5120 + ks*2560 + (wm + mt*16 + a_r)*20 + kc + a_c);
            }
#pragma unroll
            for (int np = 0; np < 2; np++) {
                ldsm_x4(bhf[np], dsm + 10240 + st*2560        + (wn + np*16 + b_r)*20 + kc + b_c);
                ldsm_x4(blf[np], dsm + 10240 + st*2560 + 1280 + (wn + np*16 + b_r)*20 + kc + b_c);
            }
            MMA_STEP_PRODMAJOR(acc, ah, al, bhf, blf);
        }

        if (ks == 1) {
            // -------- epilogue for n-tile ni: per (mt, rh) row: chunk max,
            // p' = exp(v - max), sum, store p' and chunk stats.
            bool mz[4][2];
#pragma unroll
            for (int nt = 0; nt < 4; nt++) {
                const int lc = ni*64 + wn + nt*8 + tig*2;
                mz[nt][0] = (smask[lc] == 0);
                mz[nt][1] = (smask[lc+1] == 0);
            }
            const int chunkidx = blockIdx.x*8 + ni*2 + hf;
#pragma unroll
            for (int mt = 0; mt < 2; mt++) {
#pragma unroll
                for (int rh = 0; rh < 2; rh++) {
                    float vv[8];
#pragma unroll
                    for (int nt = 0; nt < 4; nt++) {
                        vv[nt*2]   = mz[nt][0] ? neg_inf() : acc[mt][nt][rh*2];
                        vv[nt*2+1] = mz[nt][1] ? neg_inf() : acc[mt][nt][rh*2+1];
                    }
                    float mx = vv[0];
#pragma unroll
                    for (int i = 1; i < 8; i++) mx = fmaxf(mx, vv[i]);
                    mx = fmaxf(mx, __shfl_xor_sync(0xffffffffu, mx, 1));
                    mx = fmaxf(mx, __shfl_xor_sync(0xffffffffu, mx, 2));

                    float p[8];
                    float s = 0.0f;
#pragma unroll
                    for (int i = 0; i < 8; i++) {
                        p[i] = (vv[i] == neg_inf()) ? 0.0f : __expf(vv[i] - mx);
                        s += p[i];
                    }
                    s += __shfl_xor_sync(0xffffffffu, s, 1);
                    s += __shfl_xor_sync(0xffffffffu, s, 2);

                    const int r = m0 + wm + mt*16 + rh*8 + gid;
                    float* dst = Cb + (size_t)r * S_ + nbase + ni*64 + wn + tig*2;
#pragma unroll
                    for (int nt = 0; nt < 4; nt++)
                        *(float2*)(dst + nt*8) = make_float2(p[nt*2], p[nt*2+1]);

                    if (tig == 0) {
                        const size_t o = (size_t)chunkidx * TOTROWS
                                       + (size_t)bh * S_ + r;
                        cmax[o] = mx;
                        csum[o] = s;
                    }
                }
            }
        }

        // ---- store B it+1 into stage st^1
        if (it + 1 < 8) {
            unsigned* BH = dsm + 10240 + (st^1)*2560;
            unsigned* BL = BH + 1280;
#pragma unroll
            for (int j = 0; j < 2; j++) {
                unsigned h, l;
                split2(wb[j].x, wb[j].y, h, l);
                BH[br*20 + bg*4 + 2*j]   = h;  BL[br*20 + bg*4 + 2*j]   = l;
                split2(wb[j].z, wb[j].w, h, l);
                BH[br*20 + bg*4 + 2*j+1] = h;  BL[br*20 + bg*4 + 2*j+1] = l;
            }
        }
        __syncthreads();
    }
}

// ======================================================================
// combine NCHUNK=64 chunk partials per row -> rowmax, rowinv
// (chunk-major storage -> coalesced reads)
// ======================================================================
__global__ __launch_bounds__(256)
void chunk_reduce(const float* __restrict__ cmax,
                  const float* __restrict__ csum,
                  float* __restrict__ gmax,
                  float* __restrict__ ginv)
{
    const int r = blockIdx.x * 256 + threadIdx.x;
    if (r >= TOTROWS) return;
    float M = neg_inf(), S = 0.0f;
#pragma unroll 8
    for (int c = 0; c < NCHUNK; c++) {
        const float m = cmax[(size_t)c * TOTROWS + r];
        const float s = csum[(size_t)c * TOTROWS + r];
        if (m > M) { S = S * __expf(M - m) + s; M = m; }
        else if (m != neg_inf()) { S += s * __expf(m - M); }
    }
    gmax[r] = M;
    ginv[r] = 1.0f / S;
}

// ======================================================================
// ctx: attn holds p' = exp(x - chunk_max). Normalize with one scalar
// per (row, slab): sc = exp(chunk_max - M) * inv. No per-element exp.
// Writes final probs back. grid (16, 24)
// ======================================================================
__global__ __launch_bounds__(256, 2)
void ctx_bf16(float* __restrict__ attn,
              const unsigned* __restrict__ Vth,
              const unsigned* __restrict__ Vtl,
              const float* __restrict__ cmax,
              const float* __restrict__ gmax,
              const float* __restrict__ ginv,
              float* __restrict__ ctx)
{
    extern __shared__ unsigned dsm[];

    const int t = threadIdx.x, wid = t >> 5, lane = t & 31;
    const int gid = lane >> 2, tig = lane & 3;
    const int m0 = blockIdx.x * 128;
    const int bh = blockIdx.y;
    const int b  = bh / H_, h = bh % H_;
    const int wm = (wid & 3) * 32, wd = (wid >> 2) * 32;

    const int a_r = lane & 15, a_c = ((lane >> 4) & 1) * 4;
    const int b_r = (lane & 7) + ((lane >> 4) & 1) * 8;
    const int b_c = ((lane >> 3) & 1) * 4;

    const int lr = t >> 1, lg = t & 1;
    const int vr = t >> 2, vg = t & 3;

    const size_t grow = (size_t)bh * S_ + m0 + lr;
    float* Ap = attn + grow * S_ + lg * 16;
    const unsigned* VthB = Vth + ((size_t)bh * DEP_ + vr) * (S_/2) + vg * 4;
    const unsigned* VtlB = Vtl + ((size_t)bh * DEP_ + vr) * (S_/2) + vg * 4;

    const float mr = gmax[grow];
    const float ir = ginv[grow];

    float acc[2][4][4];
#pragma unroll
    for (int i = 0; i < 2; i++)
#pragma unroll
        for (int j = 0; j < 4; j++)
#pragma unroll
            for (int q = 0; q < 4; q++) acc[i][j][q] = 0.0f;

    float4 av[4];
    uint4 vh4, vl4;
    float cm;

    // ---- prologue: slab 0 -> stage 0
#pragma unroll
    for (int j = 0; j < 4; j++) av[j] = *(const float4*)(Ap + j * 4);
    vh4 = *(const uint4*)(VthB);
    vl4 = *(const uint4*)(VtlB);
    cm  = cmax[grow];               // chunk 0
    {
        const float sc = (cm == neg_inf()) ? 0.0f : __expf(cm - mr) * ir;
        unsigned* AH = dsm;          unsigned* AL = dsm + 2560;
        unsigned* VH = dsm + 10240;  unsigned* VL = dsm + 10240 + 1280;
#pragma unroll
        for (int j = 0; j < 4; j++) {
            float4 pv;
            pv.x = av[j].x * sc;
            pv.y = av[j].y * sc;
            pv.z = av[j].z * sc;
            pv.w = av[j].w * sc;
            *(float4*)(Ap + j * 4) = pv;       // final normalized attn
            unsigned hh, ll;
            split2(pv.x, pv.y, hh, ll);
            AH[lr*20 + lg*8 + 2*j]   = hh;  AL[lr*20 + lg*8 + 2*j]   = ll;
            split2(pv.z, pv.w, hh, ll);
            AH[lr*20 + lg*8 + 2*j+1] = hh;  AL[lr*20 + lg*8 + 2*j+1] = ll;
        }
        *(uint4*)&VH[vr*20 + vg*4] = vh4;
        *(uint4*)&VL[vr*20 + vg*4] = vl4;
    }
    __syncthreads();

#pragma unroll 1
    for (int i = 0; i < 64; i++) {
        const int st = i & 1;

        if (i + 1 < 64) {
            const int nc = (i + 1) * 32;
#pragma unroll
            for (int j = 0; j < 4; j++) av[j] = *(const float4*)(Ap + nc + j * 4);
            vh4 = *(const uint4*)(VthB + nc/2);
            vl4 = *(const uint4*)(VtlB + nc/2);
            cm  = cmax[(size_t)(i + 1) * TOTROWS + grow];
        }

        // ---- mma from stage st
#pragma unroll
        for (int step = 0; step < 2; step++) {
            const int kc = step * 8;
            unsigned ah[2][4], al[2][4], bhf[2][4], blf[2][4];
#pragma unroll
            for (int mt = 0; mt < 2; mt++) {
                ldsm_x4(ah[mt], dsm + st*5120        + (wm + mt*16 + a_r)*20 + kc + a_c);
                ldsm_x4(al[mt], dsm + st*5120 + 2560 + (wm + mt*16 + a_r)*20 + kc + a_c);
            }
#pragma unroll
            for (int np = 0; np < 2; np++) {
                ldsm_x4(bhf[np], dsm + 10240 + st*2560        + (wd + np*16 + b_r)*20 + kc + b_c);
                ldsm_x4(blf[np], dsm + 10240 + st*2560 + 1280 + (wd + np*16 + b_r)*20 + kc + b_c);
            }
            MMA_STEP_PRODMAJOR(acc, ah, al, bhf, blf);
        }

        // ---- process slab i+1 -> stage st^1
        if (i + 1 < 64) {
            const int nc = (i + 1) * 32;
            const float sc = (cm == neg_inf()) ? 0.0f : __expf(cm - mr) * ir;
            const unsigned ab = (st ^ 1) * 5120;
            unsigned* AH = dsm + ab;            unsigned* AL = dsm + ab + 2560;
            unsigned* VH = dsm + 10240 + (st^1)*2560;
            unsigned* VL = VH + 1280;
#pragma unroll
            for (int j = 0; j < 4; j++) {
                float4 pv;
                pv.x = av[j].x * sc;
                pv.y = av[j].y * sc;
                pv.z = av[j].z * sc;
                pv.w = av[j].w * sc;
                *(float4*)(Ap + nc + j * 4) = pv;
                unsigned hh, ll;
                split2(pv.x, pv.y, hh, ll);
                AH[lr*20 + lg*8 + 2*j]   = hh;  AL[lr*20 + lg*8 + 2*j]   = ll;
                split2(pv.z, pv.w, hh, ll);
                AH[lr*20 + lg*8 + 2*j+1] = hh;  AL[lr*20 + lg*8 + 2*j+1] = ll;
            }
            *(uint4*)&VH[vr*20 + vg*4] = vh4;
            *(uint4*)&VL[vr*20 + vg*4] = vl4;
        }
        __syncthreads();
    }

#pragma unroll
    for (int mt = 0; mt < 2; mt++) {
#pragma unroll
        for (int dt = 0; dt < 4; dt++) {
            const int r0 = m0 + wm + mt*16 + gid;
            const int r1 = r0 + 8;
            const int d  = wd + dt*8 + tig*2;
            float2 v0 = {acc[mt][dt][0], acc[mt][dt][1]};
            float2 v1 = {acc[mt][dt][2], acc[mt][dt][3]};
            *(float2*)(ctx + ((size_t)b * S_ + r0) * D_ + h * DEP_ + d) = v0;
            *(float2*)(ctx + ((size_t)b * S_ + r1) * D_ + h * DEP_ + d) = v1;
        }
    }
}

// ======================================================================
extern "C" void kernel_launch(void* const* d_in, const int* in_sizes, int n_in,
                              void* d_out, int out_size)
{
    const float* q    = (const float*)d_in[0];
    const float* k    = (const float*)d_in[1];
    const float* v    = (const float*)d_in[2];
    const int*   mask = (const int*)  d_in[3];
    const float* wq_w = (const float*)d_in[4];
    const float* wq_b = (const float*)d_in[5];
    const float* wk_w = (const float*)d_in[6];
    const float* wk_b = (const float*)d_in[7];
    const float* wv_w = (const float*)d_in[8];
    const float* wv_b = (const float*)d_in[9];
    const float* wo_w = (const float*)d_in[10];
    const float* wo_b = (const float*)d_in[11];
    float* out = (float*)d_out;

    float *Qp, *Kp, *ctxp, *rmax, *rinv, *cmax, *csum, *attn_s;
    unsigned *Vth, *Vtl;
    cudaGetSymbolAddress((void**)&Qp,     g_Qp);
    cudaGetSymbolAddress((void**)&Kp,     g_Kp);
    cudaGetSymbolAddress((void**)&ctxp,   g_ctx);
    cudaGetSymbolAddress((void**)&rmax,   g_rowmax);
    cudaGetSymbolAddress((void**)&rinv,   g_rowinv);
    cudaGetSymbolAddress((void**)&cmax,   g_cmax);
    cudaGetSymbolAddress((void**)&csum,   g_csum);
    cudaGetSymbolAddress((void**)&Vth,    g_Vth);
    cudaGetSymbolAddress((void**)&Vtl,    g_Vtl);
    cudaGetSymbolAddress((void**)&attn_s, g_attn_scratch);

    const long long need = (long long)OUT_ELEMS + (long long)ATTN_ELEMS;
    float* attn = ((long long)out_size >= need) ? (out + OUT_ELEMS) : attn_s;

    cudaFuncSetAttribute(gemm_xwT_bf16,
                         cudaFuncAttributeMaxDynamicSharedMemorySize, DYN_SMEM_BYTES);
    cudaFuncSetAttribute(logits_bf16,
                         cudaFuncAttributeMaxDynamicSharedMemorySize, DYN_SMEM_BYTES);
    cudaFuncSetAttribute(ctx_bf16,
                         cudaFuncAttributeMaxDynamicSharedMemorySize, DYN_SMEM_BYTES);

    // Fused Q/K/V projections (one launch, grid.z = 3)
    dim3 pgrid3(D_/64, MROWS/128, 3);
    gemm_xwT_bf16<<<pgrid3, 256, DYN_SMEM_BYTES>>>(
        q, k, v, wq_w, wk_w, wv_w, wq_b, wk_b, wv_b,
        Qp, Kp, Vth, Vtl, D_, D_, 1);

    // logits -> p' = exp(x - chunk_max), chunk stats
    logits_bf16<<<dim3(S_/256, S_/128, BH_), 256, DYN_SMEM_BYTES>>>(
        Qp, Kp, mask, attn, cmax, csum);

    // combine chunk partials -> row stats
    chunk_reduce<<<dim3((TOTROWS + 255)/256), 256>>>(cmax, csum, rmax, rinv);

    // ctx = softmax @ V; per-slab scalar rescale, no per-element exp
    ctx_bf16<<<dim3(S_/128, BH_), 256, DYN_SMEM_BYTES>>>(
        attn, Vth, Vtl, cmax, rmax, rinv, ctxp);

    // output projection
    dim3 pgrid1(D_/64, MROWS/128, 1);
    gemm_xwT_bf16<<<pgrid1, 256, DYN_SMEM_BYTES>>>(
        ctxp, nullptr, nullptr, wo_w, nullptr, nullptr, wo_b, nullptr, nullptr,
        out, nullptr, nullptr, nullptr, D_, D_, 0);
}